// round 8
// baseline (speedup 1.0000x reference)
#include <cuda_runtime.h>
#include <cuda_bf16.h>
#include <cstdint>
#include <cstddef>

#define B     32
#define TSEQ  128
#define H     256
#define BH    (B*H)      // 8192
#define NBLK  128

// ---------------- device scratch (no runtime allocations allowed) ----------------
__device__ __align__(16) float g_hs_e[(TSEQ+1)*BH];   // encoder h, slot 0 = h0
__device__ __align__(16) float g_hs_d[(TSEQ+1)*BH];   // decoder h, slot 0 = e_hs
__device__ __align__(16) float g_c0_d[BH];            // decoder initial c (= e_cs)
__device__ __align__(16) float g_e2T[B*H*TSEQ];       // e2 transposed: [b][h][j]
__device__ __align__(16) float g_d2 [B*TSEQ*H];       // d2: [b][i][h]
__device__ unsigned g_cnt[2];                         // global barrier counters

// ---------------- fast-math helpers ----------------
__device__ __forceinline__ float fex2(float x){
    float y; asm("ex2.approx.f32 %0, %1;" : "=f"(y) : "f"(x)); return y;
}
__device__ __forceinline__ float frcp_raw(float x){
    float y; asm("rcp.approx.f32 %0, %1;" : "=f"(y) : "f"(x)); return y;
}
// reciprocal + one Newton step (~1 ulp)
__device__ __forceinline__ float frcp1(float d){
    float r = frcp_raw(d);
    return r * __fmaf_rn(-d, r, 2.0f);
}
__device__ __forceinline__ float fsig(float x){
    // 1/(1+exp(-x)) = 1/(1+2^(-x*log2e))
    float e = fex2(fminf(-1.4426950408889634f * x, 126.0f));
    return frcp1(1.0f + e);
}
__device__ __forceinline__ float ftanh(float x){
    // tanh(x) = 1 - 2/(1+exp(2x)) = 1 - 2/(1+2^(2x*log2e))
    float e = fex2(fminf(2.8853900817779268f * x, 126.0f));
    return __fmaf_rn(-2.0f, frcp1(1.0f + e), 1.0f);
}

// ---------------- per-replay state reset ----------------
__global__ void reset_kernel(){
    int i = blockIdx.x * blockDim.x + threadIdx.x;
    if (i < BH) g_hs_e[i] = 0.0f;   // encoder h0 = zeros
    if (i < 2)  g_cnt[i]  = 0u;     // barrier counters
}

// ---------------- persistent LSTM (128 co-resident blocks, global barrier) ----------------
// Block bx owns hidden units {2bx, 2bx+1}. Thread tid = b*8 + ju*4 + gate
// computes one 256-long gate dot per step. Gate order i,f,g,o (rows gate*H+j).
__global__ void __launch_bounds__(256, 1) lstm_kernel(
    const float* __restrict__ x,      // [B, TSEQ]
    const float* __restrict__ Wih,    // [4H, 1]
    const float* __restrict__ Whh,    // [4H, H]
    const float* __restrict__ bih,    // [4H]
    const float* __restrict__ bhh,    // [4H]
    const int*   __restrict__ seq_m,  // [B] (encoder only; null for decoder)
    int phase)                        // 0 = encoder, 1 = decoder
{
    __shared__ __align__(16) float hsm[32*260];   // staged h(t), padded rows
    __shared__ __align__(16) float wsm[8*260];    // this block's 8 Whh rows

    const int tid   = threadIdx.x;
    const int b     = tid >> 3;
    const int r     = tid & 7;          // ju*4 + gate
    const int gate  = r & 3;
    const int jglob = 2*(int)blockIdx.x + (r >> 2);

    float*    hs  = phase ? g_hs_d : g_hs_e;
    unsigned* cnt = &g_cnt[phase];

    // stage this block's 8 Whh rows (coalesced: row = it, col = tid)
    #pragma unroll
    for (int it = 0; it < 8; it++){
        int grow_it = (it & 3)*H + 2*(int)blockIdx.x + (it >> 2);
        wsm[it*260 + tid] = Whh[grow_it*H + tid];
    }

    const int   grow   = gate*H + jglob;
    const float bias_r = bih[grow] + bhh[grow];
    const float wih_r  = Wih[grow];
    const float* xrow  = x + b*TSEQ;

    float c = 0.0f;
    int lastb = -1;
    if (gate == 0){
        if (phase) c = g_c0_d[b*H + jglob];
        else       lastb = seq_m[b] - 1;
    }
    __syncthreads();

    for (int t = 0; t < TSEQ; t++){
        // stage h(t) from L2 (coherent point: stcg writes / ldcg reads)
        const float4* src = (const float4*)(hs + (size_t)t*BH);
        #pragma unroll
        for (int w = 0; w < 8; w++){
            int i4 = w*256 + tid;                 // float4 index, 0..2047
            float4 hv = __ldcg(src + i4);
            int elem = i4 << 2;
            int bb = elem >> 8, kk = elem & 255;
            *(float4*)&hsm[bb*260 + kk] = hv;
        }
        __syncthreads();

        // 256-long dot, float4, 4 independent chains
        const float4* hp = (const float4*)&hsm[b*260];
        const float4* wp = (const float4*)&wsm[r*260];
        float a0=0.f, a1=0.f, a2=0.f, a3=0.f;
        #pragma unroll 8
        for (int k = 0; k < 64; k++){
            float4 hv = hp[k], wv = wp[k];
            a0 = __fmaf_rn(hv.x, wv.x, a0);
            a1 = __fmaf_rn(hv.y, wv.y, a1);
            a2 = __fmaf_rn(hv.z, wv.z, a2);
            a3 = __fmaf_rn(hv.w, wv.w, a3);
        }
        float gv = __fmaf_rn(wih_r, xrow[t], bias_r) + ((a0+a1)+(a2+a3));

        // gather the 4 gates of (b, ju): they sit on 4 consecutive lanes
        unsigned lane = (unsigned)tid & 31u;
        unsigned base = lane & ~3u;
        float gi = __shfl_sync(0xffffffffu, gv, base+0);
        float gf = __shfl_sync(0xffffffffu, gv, base+1);
        float gg = __shfl_sync(0xffffffffu, gv, base+2);
        float go = __shfl_sync(0xffffffffu, gv, base+3);

        if (gate == 0){
            float ig = fsig(gi), fg = fsig(gf), og = fsig(go);
            float gt = ftanh(gg);
            c = __fmaf_rn(fg, c, ig*gt);
            float hval = og * ftanh(c);
            __stcg(&hs[(size_t)(t+1)*BH + b*H + jglob], hval);
            if (!phase && t == lastb){      // encoder state at last valid step
                g_hs_d[b*H + jglob] = hval; // decoder h0
                g_c0_d[b*H + jglob] = c;    // decoder c0
            }
        }

        // device-wide barrier between steps (skip after last)
        if (t < TSEQ-1){
            __threadfence();
            __syncthreads();
            if (tid == 0){
                atomicAdd(cnt, 1u);
                unsigned target = (unsigned)NBLK * (unsigned)(t+1);
                while (*((volatile unsigned*)cnt) < target) { }
                __threadfence();
            }
            __syncthreads();
        }
    }
}

// ---------------- projection GEMM: out[m][h] = dot(A[m,:], W[h,:]) + bias[h] ----------------
// M=4096 (m = b*128 + s), N=256, K=256.  A[m][k] = hs[(s+1)*BH + b*H + k].
// dec==0 -> write g_e2T[b][h][j];  dec==1 -> write g_d2[(b*128+i)][h].
__global__ void __launch_bounds__(256) proj_kernel(
    const float* __restrict__ W,     // [H, H]
    const float* __restrict__ bias,  // [H]
    int dec)
{
    __shared__ __align__(16) float As[16][68];
    __shared__ __align__(16) float Bs[16][68];

    const int tid = threadIdx.x;
    const int h0  = blockIdx.x * 64;
    const int m0  = blockIdx.y * 64;

    const int mm = tid >> 2;      // 0..63 (load row within tile)
    const int kq = tid & 3;       // 0..3  (16B chunk within 16-k slab)
    const int tm = tid & 15;      // micro-tile m group
    const int tn = tid >> 4;      // micro-tile h group

    const float* hsrc = dec ? g_hs_d : g_hs_e;
    // A row pointer fixed per thread
    {
    }
    const int m_load = m0 + mm;
    const int b_l = m_load >> 7, s_l = m_load & 127;
    const float* arow = hsrc + (size_t)(s_l+1)*BH + b_l*H;
    const float* brow = W + (size_t)(h0 + mm)*H;

    float C[4][4];
    #pragma unroll
    for (int i=0;i<4;i++)
        #pragma unroll
        for (int j=0;j<4;j++) C[i][j]=0.f;

    for (int k0 = 0; k0 < H; k0 += 16){
        float4 av = *(const float4*)(arow + k0 + kq*4);
        float4 bv = *(const float4*)(brow + k0 + kq*4);
        float at[4] = {av.x,av.y,av.z,av.w};
        float bt[4] = {bv.x,bv.y,bv.z,bv.w};
        #pragma unroll
        for (int s=0;s<4;s++){
            As[kq*4+s][mm] = at[s];
            Bs[kq*4+s][mm] = bt[s];
        }
        __syncthreads();
        #pragma unroll
        for (int kk=0;kk<16;kk++){
            float4 a4 = *(const float4*)&As[kk][tm*4];
            float4 b4 = *(const float4*)&Bs[kk][tn*4];
            C[0][0]=__fmaf_rn(a4.x,b4.x,C[0][0]); C[0][1]=__fmaf_rn(a4.x,b4.y,C[0][1]);
            C[0][2]=__fmaf_rn(a4.x,b4.z,C[0][2]); C[0][3]=__fmaf_rn(a4.x,b4.w,C[0][3]);
            C[1][0]=__fmaf_rn(a4.y,b4.x,C[1][0]); C[1][1]=__fmaf_rn(a4.y,b4.y,C[1][1]);
            C[1][2]=__fmaf_rn(a4.y,b4.z,C[1][2]); C[1][3]=__fmaf_rn(a4.y,b4.w,C[1][3]);
            C[2][0]=__fmaf_rn(a4.z,b4.x,C[2][0]); C[2][1]=__fmaf_rn(a4.z,b4.y,C[2][1]);
            C[2][2]=__fmaf_rn(a4.z,b4.z,C[2][2]); C[2][3]=__fmaf_rn(a4.z,b4.w,C[2][3]);
            C[3][0]=__fmaf_rn(a4.w,b4.x,C[3][0]); C[3][1]=__fmaf_rn(a4.w,b4.y,C[3][1]);
            C[3][2]=__fmaf_rn(a4.w,b4.z,C[3][2]); C[3][3]=__fmaf_rn(a4.w,b4.w,C[3][3]);
        }
        __syncthreads();
    }

    // add bias (per h column)
    float bc[4];
    #pragma unroll
    for (int j=0;j<4;j++) bc[j] = bias[h0 + tn*4 + j];
    #pragma unroll
    for (int i=0;i<4;i++)
        #pragma unroll
        for (int j=0;j<4;j++) C[i][j] += bc[j];

    if (dec){
        #pragma unroll
        for (int i=0;i<4;i++){
            int m = m0 + tm*4 + i;
            float4 v4 = make_float4(C[i][0],C[i][1],C[i][2],C[i][3]);
            *(float4*)&g_d2[(size_t)m*H + h0 + tn*4] = v4;
        }
    } else {
        #pragma unroll
        for (int i=0;i<4;i++){
            int m = m0 + tm*4 + i;
            int bb = m >> 7, jj = m & 127;
            float* dst = g_e2T + (size_t)bb*(H*TSEQ) + jj;
            #pragma unroll
            for (int j=0;j<4;j++)
                dst[(size_t)(h0 + tn*4 + j)*TSEQ] = C[i][j];
        }
    }
}

// ---------------- attention + masked softmax ----------------
// grid (16, 32): blockIdx.y = b, blockIdx.x = i-tile of 8. 128 threads, j = tid.
__global__ void __launch_bounds__(128) attn_kernel(
    const float* __restrict__ seq,   // [B, T_E]
    const float* __restrict__ v,     // [H]
    float* __restrict__ out)         // [B, T_D, T_E]
{
    __shared__ float d2s[8*H];
    __shared__ float vsm[H];
    __shared__ float redm[4];
    __shared__ float reds[4];

    const int tid = threadIdx.x;     // j
    const int b   = blockIdx.y;
    const int i0  = blockIdx.x * 8;

    for (int idx = tid; idx < 8*H; idx += 128){
        int ii = idx >> 8, h = idx & 255;
        d2s[ii*H + h] = g_d2[(size_t)(b*TSEQ + i0 + ii)*H + h];
    }
    for (int idx = tid; idx < H; idx += 128) vsm[idx] = v[idx];
    __syncthreads();

    const float* erow = g_e2T + (size_t)b*(H*TSEQ) + tid;
    float acc[8];
    #pragma unroll
    for (int ii=0;ii<8;ii++) acc[ii]=0.f;

    #pragma unroll 4
    for (int h = 0; h < H; h++){
        float ev = erow[(size_t)h*TSEQ];
        float vh = vsm[h];
        #pragma unroll
        for (int ii=0;ii<8;ii++){
            float t = ftanh(ev + d2s[ii*H + h]);
            acc[ii] = __fmaf_rn(vh, t, acc[ii]);
        }
    }

    // mask: seq with [:,0] forced to 0.1; padded (==0) positions get -1000
    float sv = seq[b*TSEQ + tid];
    bool valid = (tid == 0) || (sv != 0.0f);
    float madd = valid ? 0.0f : -1000.0f;
    #pragma unroll
    for (int ii=0;ii<8;ii++) acc[ii] += madd;

    const unsigned lane = (unsigned)tid & 31u;
    const int wid = tid >> 5;

    for (int ii = 0; ii < 8; ii++){
        float m = acc[ii];
        #pragma unroll
        for (int off=16; off; off>>=1)
            m = fmaxf(m, __shfl_xor_sync(0xffffffffu, m, off));
        if (lane == 0) redm[wid] = m;
        __syncthreads();
        m = fmaxf(fmaxf(redm[0],redm[1]), fmaxf(redm[2],redm[3]));

        float e = fex2(1.4426950408889634f * (acc[ii] - m));
        float s = e;
        #pragma unroll
        for (int off=16; off; off>>=1)
            s += __shfl_xor_sync(0xffffffffu, s, off);
        if (lane == 0) reds[wid] = s;
        __syncthreads();
        s = (reds[0]+reds[1]) + (reds[2]+reds[3]);

        out[(size_t)(b*TSEQ + i0 + ii)*TSEQ + tid] = e * frcp1(s);
        __syncthreads();   // protect redm/reds for next ii
    }
}

// ---------------- launcher ----------------
extern "C" void kernel_launch(void* const* d_in, const int* in_sizes, int n_in,
                              void* d_out, int out_size)
{
    const float* seq    = (const float*)d_in[0];
    const int*   seq_m  = (const int*)  d_in[1];
    const float* target = (const float*)d_in[2];
    const float* Wih_e  = (const float*)d_in[3];
    const float* Whh_e  = (const float*)d_in[4];
    const float* bih_e  = (const float*)d_in[5];
    const float* bhh_e  = (const float*)d_in[6];
    const float* Wih_d  = (const float*)d_in[7];
    const float* Whh_d  = (const float*)d_in[8];
    const float* bih_d  = (const float*)d_in[9];
    const float* bhh_d  = (const float*)d_in[10];
    const float* We     = (const float*)d_in[11];
    const float* be     = (const float*)d_in[12];
    const float* Wd     = (const float*)d_in[13];
    const float* bd     = (const float*)d_in[14];
    const float* v      = (const float*)d_in[15];
    float* out = (float*)d_out;

    reset_kernel<<<(BH + 255)/256, 256>>>();
    lstm_kernel<<<NBLK, 256>>>(seq,    Wih_e, Whh_e, bih_e, bhh_e, seq_m,   0);
    lstm_kernel<<<NBLK, 256>>>(target, Wih_d, Whh_d, bih_d, bhh_d, nullptr, 1);
    proj_kernel<<<dim3(4,64), 256>>>(We, be, 0);   // -> g_e2T
    proj_kernel<<<dim3(4,64), 256>>>(Wd, bd, 1);   // -> g_d2
    attn_kernel<<<dim3(16,32), 128>>>(seq, v, out);
}